// round 9
// baseline (speedup 1.0000x reference)
#include <cuda_runtime.h>

// out[b,e] = sparsity[b,e] * sum_h ( sum_m hidden[b,m,h] ) * ( sum_n weight[e,h,n] )
// A=1, B=32, M=32, H=1024, E=8, N=1024.
//
// SINGLE kernel, no inter-block waits. Block (chunk, half):
//   h0 = chunk*8 (128 chunks), n-range = half*512..+512 (2 halves) -> 256 blocks.
//   Phase W: warp e sums its 8 weight rows (n-half)  -> smem ws[8][8]
//   Phase H: block sums hidden[b, m, h0..h0+8) over m -> smem hs[32][8]
//   Phase D: thread (b,e) dots 8 h's, RED into persistent g_accum[256].
//   Tail: last block (done counter) writes out = accum * sparsity, resets scratch.

#define Bn 32
#define Mn 32
#define Hn 1024
#define En 8
#define Nn 1024
#define NBLK 256

__device__ float g_accum[Bn * En];   // zero-initialized at load; reset each run
__device__ int   g_done = 0;

__global__ void __launch_bounds__(256) einsum_fused_kernel(
    const float* __restrict__ hidden,
    const float* __restrict__ sparsity,
    const float* __restrict__ weight,
    float* __restrict__ out)
{
    const int tid  = threadIdx.x;
    const int lane = tid & 31;
    const int wid  = tid >> 5;          // = e for phase W
    const int bid  = blockIdx.x;
    const int h0   = (bid >> 1) * 8;    // h-chunk base
    const int half = bid & 1;           // n-half

    __shared__ float  sm_ws[8][8];      // ws[e][hh]
    __shared__ float4 sm_hp[32][8][2];  // per-(b, m-group) partial, 8 h floats
    __shared__ float  sm_hs[32][8];     // hs[b][hh]
    __shared__ int    sm_last;

    // ---- Phase W: warp `wid` handles e = wid; 8 rows x 512 floats (n-half) ----
    {
        const float4* W4 = reinterpret_cast<const float4*>(weight);
        const size_t rowbase = (size_t)(wid * Hn + h0) * (Nn / 4) + half * 128;
        float s[8] = {0.f, 0.f, 0.f, 0.f, 0.f, 0.f, 0.f, 0.f};
        #pragma unroll
        for (int hh = 0; hh < 8; hh++) {
            #pragma unroll
            for (int k = 0; k < 4; k++) {   // 512 floats = 128 float4 / 32 lanes
                float4 v = W4[rowbase + (size_t)hh * (Nn / 4) + lane + k * 32];
                s[hh] += (v.x + v.y) + (v.z + v.w);
            }
        }
        #pragma unroll
        for (int off = 16; off > 0; off >>= 1)
            #pragma unroll
            for (int hh = 0; hh < 8; hh++)
                s[hh] += __shfl_xor_sync(0xffffffffu, s[hh], off);
        if (lane == 0) {
            #pragma unroll
            for (int hh = 0; hh < 8; hh++) sm_ws[wid][hh] = s[hh];
        }
    }

    // ---- Phase H: thread (b = tid>>3, mg = tid&7) sums 4 m-rows of 8 h floats ----
    {
        const int b  = tid >> 3;
        const int mg = tid & 7;
        const float4* H4 = reinterpret_cast<const float4*>(hidden);
        const size_t base4 = (size_t)(b * Mn + mg * 4) * (Hn / 4) + (h0 >> 2);
        float4 a0 = make_float4(0.f, 0.f, 0.f, 0.f);
        float4 a1 = make_float4(0.f, 0.f, 0.f, 0.f);
        #pragma unroll
        for (int mm = 0; mm < 4; mm++) {      // 8 independent LDG.128
            float4 v0 = H4[base4 + (size_t)mm * (Hn / 4)];
            float4 v1 = H4[base4 + (size_t)mm * (Hn / 4) + 1];
            a0.x += v0.x; a0.y += v0.y; a0.z += v0.z; a0.w += v0.w;
            a1.x += v1.x; a1.y += v1.y; a1.z += v1.z; a1.w += v1.w;
        }
        sm_hp[b][mg][0] = a0;
        sm_hp[b][mg][1] = a1;
    }
    __syncthreads();

    // reduce over m-groups: thread (b, hh) sums 8 partials
    {
        const int b  = tid >> 3;
        const int hh = tid & 7;
        float hs = 0.f;
        #pragma unroll
        for (int mg = 0; mg < 8; mg++)
            hs += reinterpret_cast<const float*>(&sm_hp[b][mg][0])[hh];
        sm_hs[b][hh] = hs;
    }
    __syncthreads();

    // ---- Phase D: thread (b = tid>>3, e = tid&7) dots 8 h's, RED to g_accum ----
    {
        const int b = tid >> 3;
        const int e = tid & 7;
        float p = 0.f;
        #pragma unroll
        for (int hh = 0; hh < 8; hh++)
            p += sm_hs[b][hh] * sm_ws[e][hh];
        atomicAdd(&g_accum[tid], p);    // index = b*8+e = tid; 256/addr total
    }

    // ---- Tail: last block finalizes ----
    __threadfence();
    __syncthreads();
    if (tid == 0)
        sm_last = (atomicAdd(&g_done, 1) == NBLK - 1) ? 1 : 0;
    __syncthreads();
    if (sm_last) {
        __threadfence();
        const float v = __ldcg(&g_accum[tid]);     // L2 read (atomics live in L2)
        out[tid] = v * sparsity[tid];
        g_accum[tid] = 0.f;                        // reset for next graph replay
        if (tid == 0) g_done = 0;
    }
}

extern "C" void kernel_launch(void* const* d_in, const int* in_sizes, int n_in,
                              void* d_out, int out_size)
{
    const float* hidden   = (const float*)d_in[0];
    const float* sparsity = (const float*)d_in[1];
    const float* weight   = (const float*)d_in[2];
    float* out = (float*)d_out;

    einsum_fused_kernel<<<NBLK, 256>>>(hidden, sparsity, weight, out);
}